// round 9
// baseline (speedup 1.0000x reference)
#include <cuda_runtime.h>
#include <math.h>
#include <stdint.h>

#define B_    2
#define N_    4096
#define DIM_  768
#define H_    12
#define HD_   64
#define TOK   (B_ * N_)          // 8192
#define QKVN  (3 * DIM_)         // 2304

// 0.125 * log2(e): folded into Q so softmax = exp2(S)
#define QSCALE 0.18033688011112042f

// Scratch (allocation-free rule: __device__ globals)
__device__ float g_xr    [(size_t)TOK * DIM_];        // x, tf32-rounded
__device__ float g_wqkv_r[(size_t)DIM_ * QKVN];       // w_qkv [k][n], tf32-rounded
__device__ float g_wproj_r[(size_t)DIM_ * DIM_];      // w_proj [k][n], tf32-rounded
__device__ float g_Q [(size_t)B_ * H_ * N_ * HD_];    // [b,h,n,d] fp32, pre-scaled
__device__ float g_Kb[(size_t)B_ * H_ * N_ * HD_];    // [b,h,n,d] tf32 bits
__device__ float g_Vt[(size_t)B_ * H_ * HD_ * N_];    // [b,h,d,n] tf32 bits
__device__ float g_att[(size_t)TOK * DIM_];           // [token, h*64+d] tf32 bits

// ---------------------------------------------------------------------------
__device__ __forceinline__ uint32_t f2tf(float x) {
    uint32_t r; asm("cvt.rna.tf32.f32 %0, %1;" : "=r"(r) : "f"(x)); return r;
}
__device__ __forceinline__ float tf(float x) { return __uint_as_float(f2tf(x)); }
__device__ __forceinline__ float ex2f(float x) {
    float r; asm("ex2.approx.f32 %0, %1;" : "=f"(r) : "f"(x)); return r;
}
__device__ __forceinline__ void mma_tf32(float c[4], const uint32_t a[4],
                                         uint32_t b0, uint32_t b1) {
    asm volatile(
        "mma.sync.aligned.m16n8k8.row.col.f32.tf32.tf32.f32 "
        "{%0,%1,%2,%3}, {%4,%5,%6,%7}, {%8,%9}, {%0,%1,%2,%3};"
        : "+f"(c[0]), "+f"(c[1]), "+f"(c[2]), "+f"(c[3])
        : "r"(a[0]), "r"(a[1]), "r"(a[2]), "r"(a[3]), "r"(b0), "r"(b1));
}
__device__ __forceinline__ void ldsm4(uint32_t r[4], uint32_t addr) {
    asm volatile("ldmatrix.sync.aligned.m8n8.x4.shared.b16 {%0,%1,%2,%3}, [%4];"
        : "=r"(r[0]), "=r"(r[1]), "=r"(r[2]), "=r"(r[3]) : "r"(addr));
}
#define CP_ASYNC16(dst, src) \
    asm volatile("cp.async.cg.shared.global [%0], [%1], 16;" :: "r"(dst), "l"(src) : "memory")
#define CP_COMMIT() asm volatile("cp.async.commit_group;" ::: "memory")
template <int n>
__device__ __forceinline__ void cp_wait() {
    asm volatile("cp.async.wait_group %0;" :: "n"(n) : "memory");
}

// ---------------------------------------------------------------------------
// Setup: elementwise tf32 pre-round of x, w_qkv, w_proj (NO transpose).
// ---------------------------------------------------------------------------
#define NX4 (TOK * DIM_ / 4)       // 1572864
#define NQ4 (DIM_ * QKVN / 4)      //  442368
#define NP4 (DIM_ * DIM_ / 4)      //  147456
#define NSETUP4 (NX4 + NQ4 + NP4)  // 2162688

__global__ void round_setup(const float4* __restrict__ x,
                            const float4* __restrict__ wq,
                            const float4* __restrict__ wp)
{
    const int i = blockIdx.x * blockDim.x + threadIdx.x;
    float4 v;
    float4* dst;
    if (i < NX4)            { v = x[i];              dst = (float4*)g_xr + i; }
    else if (i < NX4 + NQ4) { v = wq[i - NX4];       dst = (float4*)g_wqkv_r + (i - NX4); }
    else if (i < NSETUP4)   { v = wp[i - NX4 - NQ4]; dst = (float4*)g_wproj_r + (i - NX4 - NQ4); }
    else return;
    *dst = make_float4(tf(v.x), tf(v.y), tf(v.z), tf(v.w));
}

// ---------------------------------------------------------------------------
// Tensor-core tf32 GEMM (round-6 proven structure): 128x128 tile, BK=16,
// 8 warps, register-prefetch staging. Inputs pre-rounded, so staging is plain
// float4 STS and fragments are raw bits. A frags via ldmatrix (pattern proven
// by the attention P-fragment path); B frags scalar from [k][n] smem.
// MODE 0: A=g_xr, B=g_wqkv_r, scatter QKV. MODE 1: A=g_att, B=g_wproj_r -> C.
// ---------------------------------------------------------------------------
#define APAD 20
#define BPAD 136

template <int MODE>
__global__ __launch_bounds__(256, 2)
void gemm_tc(const float* __restrict__ bias, float* __restrict__ C,
             int M, int Nn, int K)
{
    __shared__ __align__(16) float As[128 * APAD];
    __shared__ __align__(16) float Bs[16 * BPAD];

    const float* A  = (MODE == 0) ? g_xr : g_att;
    const float* Bm = (MODE == 0) ? g_wqkv_r : g_wproj_r;

    const int tid  = threadIdx.x;
    const int wid  = tid >> 5;
    const int lane = tid & 31;
    const int g = lane >> 2;
    const int t = lane & 3;
    const int bm = blockIdx.y * 128;
    const int bn = blockIdx.x * 128;
    const int mw = (wid & 3) * 32;
    const int nw = (wid >> 2) * 64;

    const int arow = tid >> 1;
    const int ak   = (tid & 1) * 8;
    const int bk   = tid >> 4;
    const int bn4  = (tid & 15) * 8;

    const uint32_t asb = (uint32_t)__cvta_generic_to_shared(As);
    // A-frag ldsm lane offset (same pattern as the proven attention P path)
    const uint32_t lmoff = (((lane & 15) * APAD) + (lane >> 4) * 4) * 4;

    float acc[2][8][4];
    #pragma unroll
    for (int mi = 0; mi < 2; mi++)
        #pragma unroll
        for (int n = 0; n < 8; n++)
            #pragma unroll
            for (int j = 0; j < 4; j++) acc[mi][n][j] = 0.0f;

    const float* Aptr = A  + (size_t)(bm + arow) * K + ak;
    const float* Bptr = Bm + (size_t)bk * Nn + bn + bn4;

    // prefetch stage 0 (register-staged, round-6 proven)
    float4 pa0 = ((const float4*)Aptr)[0];
    float4 pa1 = ((const float4*)Aptr)[1];
    float4 pb0 = ((const float4*)Bptr)[0];
    float4 pb1 = ((const float4*)Bptr)[1];

    const int nstage = K / 16;
    #pragma unroll 1
    for (int s = 0; s < nstage; ++s) {
        __syncthreads();
        {   // store stage s (data already tf32-rounded)
            float* ad = As + arow * APAD + ak;
            *(float4*)(ad)     = pa0;
            *(float4*)(ad + 4) = pa1;
            float* bd = Bs + bk * BPAD + bn4;
            *(float4*)(bd)     = pb0;
            *(float4*)(bd + 4) = pb1;
        }
        __syncthreads();

        if (s + 1 < nstage) {   // prefetch stage s+1
            const float* ap = Aptr + (s + 1) * 16;
            const float* bp = Bptr + (size_t)(s + 1) * 16 * Nn;
            pa0 = ((const float4*)ap)[0];
            pa1 = ((const float4*)ap)[1];
            pb0 = ((const float4*)bp)[0];
            pb1 = ((const float4*)bp)[1];
        }

        #pragma unroll
        for (int kk = 0; kk < 2; kk++) {
            uint32_t af[2][4];
            #pragma unroll
            for (int mi = 0; mi < 2; mi++)
                ldsm4(af[mi], asb + ((mw + mi * 16) * APAD) * 4 + kk * 32 + lmoff);
            #pragma unroll
            for (int n = 0; n < 8; n++) {
                const uint32_t b0 = __float_as_uint(Bs[(kk * 8 + t)     * BPAD + nw + n * 8 + g]);
                const uint32_t b1 = __float_as_uint(Bs[(kk * 8 + t + 4) * BPAD + nw + n * 8 + g]);
                mma_tf32(acc[0][n], af[0], b0, b1);
                mma_tf32(acc[1][n], af[1], b0, b1);
            }
        }
    }

    if (MODE == 1) {
        #pragma unroll
        for (int mi = 0; mi < 2; mi++) {
            const int r0 = bm + mw + mi * 16 + g;
            #pragma unroll
            for (int n = 0; n < 8; n++) {
                const int col = bn + nw + n * 8 + 2 * t;
                const float bb0 = bias[col], bb1 = bias[col + 1];
                *(float2*)(C + (size_t)r0 * Nn + col) =
                    make_float2(acc[mi][n][0] + bb0, acc[mi][n][1] + bb1);
                *(float2*)(C + (size_t)(r0 + 8) * Nn + col) =
                    make_float2(acc[mi][n][2] + bb0, acc[mi][n][3] + bb1);
            }
        }
    } else {
        const int region = (bn + nw) >> 6;
        const int which  = region / H_;
        const int h      = region % H_;
        #pragma unroll
        for (int mi = 0; mi < 2; mi++) {
            #pragma unroll
            for (int jr = 0; jr < 2; jr++) {
                const int row = bm + mw + mi * 16 + g + jr * 8;
                const int b   = row >> 12;
                const int ntk = row & (N_ - 1);
                #pragma unroll
                for (int n = 0; n < 8; n++) {
                    const int dd  = (nw + n * 8 + 2 * t) & 63;
                    const int col = bn + nw + n * 8 + 2 * t;
                    const float v0 = acc[mi][n][jr * 2 + 0] + bias[col];
                    const float v1 = acc[mi][n][jr * 2 + 1] + bias[col + 1];
                    if (which == 0) {
                        float* dst = g_Q + (((size_t)(b * H_ + h) * N_) + ntk) * HD_ + dd;
                        dst[0] = v0 * QSCALE; dst[1] = v1 * QSCALE;
                    } else if (which == 1) {
                        float* dst = g_Kb + (((size_t)(b * H_ + h) * N_) + ntk) * HD_ + dd;
                        dst[0] = tf(v0); dst[1] = tf(v1);
                    } else {
                        float* dst = g_Vt + (((size_t)(b * H_ + h) * HD_) + dd) * N_ + ntk;
                        dst[0]  = tf(v0);
                        dst[N_] = tf(v1);
                    }
                }
            }
        }
    }
}

// ---------------------------------------------------------------------------
// mma.sync tf32 flash attention (exact round-6 kernel; only delta: final
// g_att stores are tf32-pre-rounded for the raw-bits gemm<1> B-path).
// ---------------------------------------------------------------------------
#define PADK 68
#define KTILE_F (64 * PADK)             // 4352 floats
#define VTILE_F (64 * PADK)             // 4352 floats
#define BUF_F   (KTILE_F + VTILE_F)     // 8704 floats
#define SM_P    (2 * BUF_F)             // 17408 floats
#define ATTN_SMEM_FLOATS (SM_P + 8 * 16 * PADK)   // 26112
#define ATTN_SMEM_BYTES  (ATTN_SMEM_FLOATS * 4)   // 104448

__global__ __launch_bounds__(256, 2)
void attn_mma_kernel()
{
    extern __shared__ __align__(16) float sm[];
    const uint32_t sb = (uint32_t)__cvta_generic_to_shared(sm);

    const int tid  = threadIdx.x;
    const int wid  = tid >> 5;
    const int lane = tid & 31;
    const int g = lane >> 2;
    const int t = lane & 3;

    const int h = blockIdx.y, b = blockIdx.z;
    const int m0 = blockIdx.x * 128;
    const size_t hb = (size_t)(b * H_ + h) * N_ * HD_;

    const float* Kg  = g_Kb + hb;
    const float* Vtg = g_Vt + hb;

    const uint32_t krow = (lane & 7) + ((lane >> 4) << 3);
    const uint32_t kcol = ((lane >> 3) & 1) * 4;
    const uint32_t koff = (krow * PADK + kcol) * 4;
    const uint32_t poff = sb + (SM_P + wid * 16 * PADK) * 4
                        + ((lane & 15) * PADK + (lane >> 4) * 4) * 4;
    float* Pw = sm + SM_P + wid * 16 * PADK;

    const float* Qg = g_Q + hb + (size_t)(m0 + wid * 16) * HD_;
    uint32_t qa[8][4];
    #pragma unroll
    for (int k = 0; k < 8; k++) {
        qa[k][0] = f2tf(Qg[(size_t)g * HD_       + k * 8 + t]);
        qa[k][1] = f2tf(Qg[(size_t)(g + 8) * HD_ + k * 8 + t]);
        qa[k][2] = f2tf(Qg[(size_t)g * HD_       + k * 8 + t + 4]);
        qa[k][3] = f2tf(Qg[(size_t)(g + 8) * HD_ + k * 8 + t + 4]);
    }

    float oacc[8][4];
    #pragma unroll
    for (int n = 0; n < 8; n++)
        #pragma unroll
        for (int j = 0; j < 4; j++) oacc[n][j] = 0.0f;
    float lsum0 = 0.0f, lsum1 = 0.0f;

    {   // prefetch tile 0
        const uint32_t kdst = sb;
        const uint32_t vdst = sb + KTILE_F * 4;
        #pragma unroll
        for (int i = 0; i < 4; i++) {
            const int f = tid + i * 256;
            const int r = f >> 4, c4 = (f & 15) * 4;
            CP_ASYNC16(kdst + (r * PADK + c4) * 4, Kg + (size_t)r * HD_ + c4);
            CP_ASYNC16(vdst + (r * PADK + c4) * 4, Vtg + (size_t)r * N_ + c4);
        }
        CP_COMMIT();
    }

    #pragma unroll 1
    for (int it = 0; it < 64; ++it) {
        __syncthreads();

        if (it + 1 < 64) {
            const uint32_t bo   = ((it + 1) & 1) * BUF_F * 4;
            const uint32_t kdst = sb + bo;
            const uint32_t vdst = sb + bo + KTILE_F * 4;
            const float* Kt = Kg + (size_t)((it + 1) * 64) * HD_;
            const float* Vt = Vtg + (it + 1) * 64;
            #pragma unroll
            for (int i = 0; i < 4; i++) {
                const int f = tid + i * 256;
                const int r = f >> 4, c4 = (f & 15) * 4;
                CP_ASYNC16(kdst + (r * PADK + c4) * 4, Kt + (size_t)r * HD_ + c4);
                CP_ASYNC16(vdst + (r * PADK + c4) * 4, Vt + (size_t)r * N_ + c4);
            }
            CP_COMMIT();
            cp_wait<1>();
        } else {
            cp_wait<0>();
        }
        __syncthreads();

        const uint32_t ksb = sb + (it & 1) * BUF_F * 4;
        const uint32_t kla = ksb + koff;
        const uint32_t vla = ksb + KTILE_F * 4 + koff;

        float sacc[8][4];
        #pragma unroll
        for (int n = 0; n < 8; n++)
            #pragma unroll
            for (int j = 0; j < 4; j++) sacc[n][j] = 0.0f;

        #pragma unroll
        for (int ks = 0; ks < 8; ks++) {
            #pragma unroll
            for (int np = 0; np < 4; np++) {
                uint32_t f[4];
                ldsm4(f, kla + np * (16 * PADK * 4) + ks * 32);
                mma_tf32(sacc[2 * np],     qa[ks], f[0], f[1]);
                mma_tf32(sacc[2 * np + 1], qa[ks], f[2], f[3]);
            }
        }

        #pragma unroll
        for (int n = 0; n < 8; n++) {
            const float e0 = ex2f(sacc[n][0]);
            const float e1 = ex2f(sacc[n][1]);
            const float e2 = ex2f(sacc[n][2]);
            const float e3 = ex2f(sacc[n][3]);
            lsum0 += e0 + e1;
            lsum1 += e2 + e3;
            *(float2*)&Pw[g * PADK + n * 8 + 2 * t] = make_float2(tf(e0), tf(e1));
            *(float2*)&Pw[(g + 8) * PADK + n * 8 + 2 * t] = make_float2(tf(e2), tf(e3));
        }
        __syncwarp();

        #pragma unroll
        for (int ks = 0; ks < 8; ks++) {
            uint32_t pa[4];
            ldsm4(pa, poff + ks * 32);
            #pragma unroll
            for (int np = 0; np < 4; np++) {
                uint32_t f[4];
                ldsm4(f, vla + np * (16 * PADK * 4) + ks * 32);
                mma_tf32(oacc[2 * np],     pa, f[0], f[1]);
                mma_tf32(oacc[2 * np + 1], pa, f[2], f[3]);
            }
        }
    }

    lsum0 += __shfl_xor_sync(0xFFFFFFFF, lsum0, 1);
    lsum0 += __shfl_xor_sync(0xFFFFFFFF, lsum0, 2);
    lsum1 += __shfl_xor_sync(0xFFFFFFFF, lsum1, 1);
    lsum1 += __shfl_xor_sync(0xFFFFFFFF, lsum1, 2);
    const float inv0 = 1.0f / lsum0;
    const float inv1 = 1.0f / lsum1;

    const size_t row0 = (size_t)(b * N_ + m0 + wid * 16 + g);
    float* o0 = g_att + row0 * DIM_ + h * HD_;
    float* o1 = o0 + 8 * DIM_;
    #pragma unroll
    for (int n = 0; n < 8; n++) {
        *(float2*)(o0 + n * 8 + 2 * t) =
            make_float2(tf(oacc[n][0] * inv0), tf(oacc[n][1] * inv0));
        *(float2*)(o1 + n * 8 + 2 * t) =
            make_float2(tf(oacc[n][2] * inv1), tf(oacc[n][3] * inv1));
    }
}

// ---------------------------------------------------------------------------
extern "C" void kernel_launch(void* const* d_in, const int* in_sizes, int n_in,
                              void* d_out, int out_size)
{
    const float* x      = (const float*)d_in[0];
    const float* w_qkv  = (const float*)d_in[1];
    const float* b_qkv  = (const float*)d_in[2];
    const float* w_proj = (const float*)d_in[3];
    const float* b_proj = (const float*)d_in[4];
    float* out = (float*)d_out;

    cudaFuncSetAttribute(attn_mma_kernel,
                         cudaFuncAttributeMaxDynamicSharedMemorySize, ATTN_SMEM_BYTES);

    {   // 0) elementwise tf32 pre-round of x / w_qkv / w_proj (no transpose)
        round_setup<<<NSETUP4 / 256, 256>>>((const float4*)x,
                                            (const float4*)w_qkv,
                                            (const float4*)w_proj);
    }
    {   // 1) QKV GEMM (tensor) + head-major scatter
        dim3 grid(QKVN / 128, TOK / 128);
        gemm_tc<0><<<grid, 256>>>(b_qkv, nullptr, TOK, QKVN, DIM_);
    }
    {   // 2) mma.sync tf32 attention (round-6 proven kernel)
        dim3 grid(N_ / 128, H_, B_);
        attn_mma_kernel<<<grid, 256, ATTN_SMEM_BYTES>>>();
    }
    {   // 3) output projection (tensor)
        dim3 grid(DIM_ / 128, TOK / 128);
        gemm_tc<1><<<grid, 256>>>(b_proj, out, TOK, DIM_, DIM_);
    }
}

// round 10
// speedup vs baseline: 1.1487x; 1.1487x over previous
#include <cuda_runtime.h>
#include <cuda_fp16.h>
#include <math.h>
#include <stdint.h>

#define B_    2
#define N_    4096
#define DIM_  768
#define H_    12
#define HD_   64
#define TOK   (B_ * N_)          // 8192
#define QKVN  (3 * DIM_)         // 2304

// 0.125 * log2(e): folded into Q so softmax = exp2(S)
#define QSCALE 0.18033688011112042f

// Scratch (allocation-free rule: __device__ globals)
__device__ float  g_xr    [(size_t)TOK * DIM_];        // x, tf32-rounded
__device__ float  g_wqkv_r[(size_t)DIM_ * QKVN];       // w_qkv [k][n], tf32
__device__ float  g_wproj_r[(size_t)DIM_ * DIM_];      // w_proj [k][n], tf32
__device__ __half g_Qh[(size_t)B_ * H_ * N_ * HD_];    // [b,h,n,d] fp16, pre-scaled
__device__ __half g_Kh[(size_t)B_ * H_ * N_ * HD_];    // [b,h,n,d] fp16
__device__ float  g_Vt[(size_t)B_ * H_ * HD_ * N_];    // [b,h,d,n] tf32 bits
__device__ float  g_att[(size_t)TOK * DIM_];           // [token, h*64+d] tf32 bits

// ---------------------------------------------------------------------------
__device__ __forceinline__ uint32_t f2tf(float x) {
    uint32_t r; asm("cvt.rna.tf32.f32 %0, %1;" : "=r"(r) : "f"(x)); return r;
}
__device__ __forceinline__ float tf(float x) { return __uint_as_float(f2tf(x)); }
__device__ __forceinline__ float ex2f(float x) {
    float r; asm("ex2.approx.f32 %0, %1;" : "=f"(r) : "f"(x)); return r;
}
__device__ __forceinline__ void mma_tf32(float c[4], const uint32_t a[4],
                                         uint32_t b0, uint32_t b1) {
    asm volatile(
        "mma.sync.aligned.m16n8k8.row.col.f32.tf32.tf32.f32 "
        "{%0,%1,%2,%3}, {%4,%5,%6,%7}, {%8,%9}, {%0,%1,%2,%3};"
        : "+f"(c[0]), "+f"(c[1]), "+f"(c[2]), "+f"(c[3])
        : "r"(a[0]), "r"(a[1]), "r"(a[2]), "r"(a[3]), "r"(b0), "r"(b1));
}
__device__ __forceinline__ void mma_f16(float c[4], const uint32_t a[4],
                                        uint32_t b0, uint32_t b1) {
    asm volatile(
        "mma.sync.aligned.m16n8k16.row.col.f32.f16.f16.f32 "
        "{%0,%1,%2,%3}, {%4,%5,%6,%7}, {%8,%9}, {%0,%1,%2,%3};"
        : "+f"(c[0]), "+f"(c[1]), "+f"(c[2]), "+f"(c[3])
        : "r"(a[0]), "r"(a[1]), "r"(a[2]), "r"(a[3]), "r"(b0), "r"(b1));
}
__device__ __forceinline__ void ldsm4(uint32_t r[4], uint32_t addr) {
    asm volatile("ldmatrix.sync.aligned.m8n8.x4.shared.b16 {%0,%1,%2,%3}, [%4];"
        : "=r"(r[0]), "=r"(r[1]), "=r"(r[2]), "=r"(r[3]) : "r"(addr));
}
#define CP_ASYNC16(dst, src) \
    asm volatile("cp.async.cg.shared.global [%0], [%1], 16;" :: "r"(dst), "l"(src) : "memory")
#define CP_COMMIT() asm volatile("cp.async.commit_group;" ::: "memory")
template <int n>
__device__ __forceinline__ void cp_wait() {
    asm volatile("cp.async.wait_group %0;" :: "n"(n) : "memory");
}

// ---------------------------------------------------------------------------
// Setup: elementwise tf32 pre-round of x, w_qkv, w_proj (proven in round 9).
// ---------------------------------------------------------------------------
#define NX4 (TOK * DIM_ / 4)
#define NQ4 (DIM_ * QKVN / 4)
#define NP4 (DIM_ * DIM_ / 4)
#define NSETUP4 (NX4 + NQ4 + NP4)

__global__ void round_setup(const float4* __restrict__ x,
                            const float4* __restrict__ wq,
                            const float4* __restrict__ wp)
{
    const int i = blockIdx.x * blockDim.x + threadIdx.x;
    float4 v;
    float4* dst;
    if (i < NX4)            { v = x[i];              dst = (float4*)g_xr + i; }
    else if (i < NX4 + NQ4) { v = wq[i - NX4];       dst = (float4*)g_wqkv_r + (i - NX4); }
    else if (i < NSETUP4)   { v = wp[i - NX4 - NQ4]; dst = (float4*)g_wproj_r + (i - NX4 - NQ4); }
    else return;
    *dst = make_float4(tf(v.x), tf(v.y), tf(v.z), tf(v.w));
}

// ---------------------------------------------------------------------------
// Tensor-core tf32 GEMM (round-9 proven): 128x128 tile, BK=16, 8 warps,
// register-prefetch staging, A frags via ldmatrix, B frags scalar [k][n].
// MODE 0: A=g_xr, B=g_wqkv_r, scatter QKV (Q/K fp16, Vt tf32).
// MODE 1: A=g_att, B=g_wproj_r -> C.
// ---------------------------------------------------------------------------
#define APAD 20
#define BPAD 136

template <int MODE>
__global__ __launch_bounds__(256, 2)
void gemm_tc(const float* __restrict__ bias, float* __restrict__ C,
             int M, int Nn, int K)
{
    __shared__ __align__(16) float As[128 * APAD];
    __shared__ __align__(16) float Bs[16 * BPAD];

    const float* A  = (MODE == 0) ? g_xr : g_att;
    const float* Bm = (MODE == 0) ? g_wqkv_r : g_wproj_r;

    const int tid  = threadIdx.x;
    const int wid  = tid >> 5;
    const int lane = tid & 31;
    const int g = lane >> 2;
    const int t = lane & 3;
    const int bm = blockIdx.y * 128;
    const int bn = blockIdx.x * 128;
    const int mw = (wid & 3) * 32;
    const int nw = (wid >> 2) * 64;

    const int arow = tid >> 1;
    const int ak   = (tid & 1) * 8;
    const int bk   = tid >> 4;
    const int bn4  = (tid & 15) * 8;

    const uint32_t asb = (uint32_t)__cvta_generic_to_shared(As);
    const uint32_t lmoff = (((lane & 15) * APAD) + (lane >> 4) * 4) * 4;

    float acc[2][8][4];
    #pragma unroll
    for (int mi = 0; mi < 2; mi++)
        #pragma unroll
        for (int n = 0; n < 8; n++)
            #pragma unroll
            for (int j = 0; j < 4; j++) acc[mi][n][j] = 0.0f;

    const float* Aptr = A  + (size_t)(bm + arow) * K + ak;
    const float* Bptr = Bm + (size_t)bk * Nn + bn + bn4;

    float4 pa0 = ((const float4*)Aptr)[0];
    float4 pa1 = ((const float4*)Aptr)[1];
    float4 pb0 = ((const float4*)Bptr)[0];
    float4 pb1 = ((const float4*)Bptr)[1];

    const int nstage = K / 16;
    #pragma unroll 1
    for (int s = 0; s < nstage; ++s) {
        __syncthreads();
        {
            float* ad = As + arow * APAD + ak;
            *(float4*)(ad)     = pa0;
            *(float4*)(ad + 4) = pa1;
            float* bd = Bs + bk * BPAD + bn4;
            *(float4*)(bd)     = pb0;
            *(float4*)(bd + 4) = pb1;
        }
        __syncthreads();

        if (s + 1 < nstage) {
            const float* ap = Aptr + (s + 1) * 16;
            const float* bp = Bptr + (size_t)(s + 1) * 16 * Nn;
            pa0 = ((const float4*)ap)[0];
            pa1 = ((const float4*)ap)[1];
            pb0 = ((const float4*)bp)[0];
            pb1 = ((const float4*)bp)[1];
        }

        #pragma unroll
        for (int kk = 0; kk < 2; kk++) {
            uint32_t af[2][4];
            #pragma unroll
            for (int mi = 0; mi < 2; mi++)
                ldsm4(af[mi], asb + ((mw + mi * 16) * APAD) * 4 + kk * 32 + lmoff);
            #pragma unroll
            for (int n = 0; n < 8; n++) {
                const uint32_t b0 = __float_as_uint(Bs[(kk * 8 + t)     * BPAD + nw + n * 8 + g]);
                const uint32_t b1 = __float_as_uint(Bs[(kk * 8 + t + 4) * BPAD + nw + n * 8 + g]);
                mma_tf32(acc[0][n], af[0], b0, b1);
                mma_tf32(acc[1][n], af[1], b0, b1);
            }
        }
    }

    if (MODE == 1) {
        #pragma unroll
        for (int mi = 0; mi < 2; mi++) {
            const int r0 = bm + mw + mi * 16 + g;
            #pragma unroll
            for (int n = 0; n < 8; n++) {
                const int col = bn + nw + n * 8 + 2 * t;
                const float bb0 = bias[col], bb1 = bias[col + 1];
                *(float2*)(C + (size_t)r0 * Nn + col) =
                    make_float2(acc[mi][n][0] + bb0, acc[mi][n][1] + bb1);
                *(float2*)(C + (size_t)(r0 + 8) * Nn + col) =
                    make_float2(acc[mi][n][2] + bb0, acc[mi][n][3] + bb1);
            }
        }
    } else {
        const int region = (bn + nw) >> 6;
        const int which  = region / H_;
        const int h      = region % H_;
        #pragma unroll
        for (int mi = 0; mi < 2; mi++) {
            #pragma unroll
            for (int jr = 0; jr < 2; jr++) {
                const int row = bm + mw + mi * 16 + g + jr * 8;
                const int b   = row >> 12;
                const int ntk = row & (N_ - 1);
                #pragma unroll
                for (int n = 0; n < 8; n++) {
                    const int dd  = (nw + n * 8 + 2 * t) & 63;
                    const int col = bn + nw + n * 8 + 2 * t;
                    const float v0 = acc[mi][n][jr * 2 + 0] + bias[col];
                    const float v1 = acc[mi][n][jr * 2 + 1] + bias[col + 1];
                    const size_t nd = (((size_t)(b * H_ + h) * N_) + ntk) * HD_ + dd;
                    if (which == 0) {
                        *(__half2*)&g_Qh[nd] = __floats2half2_rn(v0 * QSCALE, v1 * QSCALE);
                    } else if (which == 1) {
                        *(__half2*)&g_Kh[nd] = __floats2half2_rn(v0, v1);
                    } else {
                        float* dst = g_Vt + (((size_t)(b * H_ + h) * HD_) + dd) * N_ + ntk;
                        dst[0]  = tf(v0);
                        dst[N_] = tf(v1);
                    }
                }
            }
        }
    }
}

// ---------------------------------------------------------------------------
// Flash attention: MMA1 fp16 (m16n8k16), MMA2 tf32 (m16n8k8).
// CTA = 256 thr (8 warps) = 128 queries x 1 head; warp owns 16 query rows.
// 64-key tiles, cp.async double-buffered, 2 CTAs/SM. No online max.
// V/P/MMA2 machinery byte-identical to the proven round-9 kernel.
// ---------------------------------------------------------------------------
#define PADK 68
#define KROWB 144                        // bytes per K row (64 fp16 + 8 pad)
#define KTILE_B (64 * KROWB)             //  9216 B
#define VTILE_B (64 * PADK * 4)          // 17408 B
#define BUF_B   (KTILE_B + VTILE_B)      // 26624 B
#define SM_P_B  (2 * BUF_B)              // 53248 B
#define ATTN_SMEM_BYTES (SM_P_B + 8 * 16 * PADK * 4)   // 88064

__global__ __launch_bounds__(256, 2)
void attn_mma_kernel()
{
    extern __shared__ __align__(16) float sm[];
    const uint32_t sb = (uint32_t)__cvta_generic_to_shared(sm);

    const int tid  = threadIdx.x;
    const int wid  = tid >> 5;
    const int lane = tid & 31;
    const int g = lane >> 2;
    const int t = lane & 3;
    const int g4 = lane >> 3;

    const int h = blockIdx.y, b = blockIdx.z;
    const int m0 = blockIdx.x * 128;
    const size_t hb = (size_t)(b * H_ + h) * N_ * HD_;

    const __half* Kg  = g_Kh + hb;
    const float*  Vtg = g_Vt + hb;

    // K fp16 ldsm lane offset: tiles = (n rows 0-7 / 8-15) x (k bytes 0-15 / 16-31)
    const uint32_t kmoff = ((lane & 7) + ((g4 >> 1) << 3)) * KROWB + (g4 & 1) * 16;
    // V tf32 ldsm lane offset (B-frag, proven round-9 pattern)
    const uint32_t vrow = (lane & 7) + ((lane >> 4) << 3);
    const uint32_t vcol = ((lane >> 3) & 1) * 4;
    const uint32_t vmoff = (vrow * PADK + vcol) * 4;
    // P tf32 ldsm lane offset (A-frag, proven round-9 pattern)
    const uint32_t poff = sb + SM_P_B + wid * (16 * PADK * 4)
                        + ((lane & 15) * PADK + (lane >> 4) * 4) * 4;
    float* Pw = sm + SM_P_B / 4 + wid * 16 * PADK;

    // --- Q fp16 fragments (4 k16-chunks x 4 regs), straight from gmem ---
    const __half* Qg = g_Qh + hb + (size_t)(m0 + wid * 16) * HD_;
    uint32_t qa[4][4];
    #pragma unroll
    for (int kt = 0; kt < 4; kt++) {
        qa[kt][0] = *(const uint32_t*)(Qg + (size_t)g * HD_       + kt * 16 + 2 * t);
        qa[kt][1] = *(const uint32_t*)(Qg + (size_t)(g + 8) * HD_ + kt * 16 + 2 * t);
        qa[kt][2] = *(const uint32_t*)(Qg + (size_t)g * HD_       + kt * 16 + 2 * t + 8);
        qa[kt][3] = *(const uint32_t*)(Qg + (size_t)(g + 8) * HD_ + kt * 16 + 2 * t + 8);
    }

    float oacc[8][4];
    #pragma unroll
    for (int n = 0; n < 8; n++)
        #pragma unroll
        for (int j = 0; j < 4; j++) oacc[n][j] = 0.0f;
    float lsum0 = 0.0f, lsum1 = 0.0f;

    {   // prefetch tile 0
        #pragma unroll
        for (int i = 0; i < 2; i++) {       // K: 512 chunks (64 rows x 8)
            const int c = tid + i * 256;
            const int r = c >> 3, q = c & 7;
            CP_ASYNC16(sb + r * KROWB + q * 16, Kg + (size_t)r * HD_ + q * 8);
        }
        #pragma unroll
        for (int i = 0; i < 4; i++) {       // V: 1024 chunks (64 rows x 16)
            const int c = tid + i * 256;
            const int r = c >> 4, q = c & 15;
            CP_ASYNC16(sb + KTILE_B + (r * PADK + q * 4) * 4,
                       Vtg + (size_t)r * N_ + q * 4);
        }
        CP_COMMIT();
    }

    #pragma unroll 1
    for (int it = 0; it < 64; ++it) {
        __syncthreads();    // all warps done with the other buffer

        if (it + 1 < 64) {
            const uint32_t bo = ((it + 1) & 1) * BUF_B;
            const __half* Kt = Kg + (size_t)((it + 1) * 64) * HD_;
            const float*  Vt = Vtg + (it + 1) * 64;
            #pragma unroll
            for (int i = 0; i < 2; i++) {
                const int c = tid + i * 256;
                const int r = c >> 3, q = c & 7;
                CP_ASYNC16(sb + bo + r * KROWB + q * 16, Kt + (size_t)r * HD_ + q * 8);
            }
            #pragma unroll
            for (int i = 0; i < 4; i++) {
                const int c = tid + i * 256;
                const int r = c >> 4, q = c & 15;
                CP_ASYNC16(sb + bo + KTILE_B + (r * PADK + q * 4) * 4,
                           Vt + (size_t)r * N_ + q * 4);
            }
            CP_COMMIT();
            cp_wait<1>();
        } else {
            cp_wait<0>();
        }
        __syncthreads();    // tile it visible

        const uint32_t ksb = sb + (it & 1) * BUF_B;
        const uint32_t kla = ksb + kmoff;
        const uint32_t vla = ksb + KTILE_B + vmoff;

        // --- MMA1 (fp16): S[16 x 64] = Q * K^T ---
        float sacc[8][4];
        #pragma unroll
        for (int n = 0; n < 8; n++)
            #pragma unroll
            for (int j = 0; j < 4; j++) sacc[n][j] = 0.0f;

        #pragma unroll
        for (int kt = 0; kt < 4; kt++) {
            #pragma unroll
            for (int jp = 0; jp < 4; jp++) {
                uint32_t f[4];
                ldsm4(f, kla + jp * (16 * KROWB) + kt * 32);
                mma_f16(sacc[2 * jp],     qa[kt], f[0], f[1]);
                mma_f16(sacc[2 * jp + 1], qa[kt], f[2], f[3]);
            }
        }

        // --- softmax: P = exp2(S) -> per-warp smem (tf32) ---
        #pragma unroll
        for (int n = 0; n < 8; n++) {
            const float e0 = ex2f(sacc[n][0]);
            const float e1 = ex2f(sacc[n][1]);
            const float e2 = ex2f(sacc[n][2]);
            const float e3 = ex2f(sacc[n][3]);
            lsum0 += e0 + e1;
            lsum1 += e2 + e3;
            *(float2*)&Pw[g * PADK + n * 8 + 2 * t] = make_float2(tf(e0), tf(e1));
            *(float2*)&Pw[(g + 8) * PADK + n * 8 + 2 * t] = make_float2(tf(e2), tf(e3));
        }
        __syncwarp();

        // --- MMA2 (tf32): O[16 x 64] += P * V ---
        #pragma unroll
        for (int ks = 0; ks < 8; ks++) {
            uint32_t pa[4];
            ldsm4(pa, poff + ks * 32);
            #pragma unroll
            for (int np = 0; np < 4; np++) {
                uint32_t f[4];
                ldsm4(f, vla + np * (16 * PADK * 4) + ks * 32);
                mma_tf32(oacc[2 * np],     pa, f[0], f[1]);
                mma_tf32(oacc[2 * np + 1], pa, f[2], f[3]);
            }
        }
    }

    lsum0 += __shfl_xor_sync(0xFFFFFFFF, lsum0, 1);
    lsum0 += __shfl_xor_sync(0xFFFFFFFF, lsum0, 2);
    lsum1 += __shfl_xor_sync(0xFFFFFFFF, lsum1, 1);
    lsum1 += __shfl_xor_sync(0xFFFFFFFF, lsum1, 2);
    const float inv0 = 1.0f / lsum0;
    const float inv1 = 1.0f / lsum1;

    const size_t row0 = (size_t)(b * N_ + m0 + wid * 16 + g);
    float* o0 = g_att + row0 * DIM_ + h * HD_;
    float* o1 = o0 + 8 * DIM_;
    #pragma unroll
    for (int n = 0; n < 8; n++) {
        *(float2*)(o0 + n * 8 + 2 * t) =
            make_float2(tf(oacc[n][0] * inv0), tf(oacc[n][1] * inv0));
        *(float2*)(o1 + n * 8 + 2 * t) =
            make_float2(tf(oacc[n][2] * inv1), tf(oacc[n][3] * inv1));
    }
}

// ---------------------------------------------------------------------------
extern "C" void kernel_launch(void* const* d_in, const int* in_sizes, int n_in,
                              void* d_out, int out_size)
{
    const float* x      = (const float*)d_in[0];
    const float* w_qkv  = (const float*)d_in[1];
    const float* b_qkv  = (const float*)d_in[2];
    const float* w_proj = (const float*)d_in[3];
    const float* b_proj = (const float*)d_in[4];
    float* out = (float*)d_out;

    cudaFuncSetAttribute(attn_mma_kernel,
                         cudaFuncAttributeMaxDynamicSharedMemorySize, ATTN_SMEM_BYTES);

    {   // 0) elementwise tf32 pre-round of x / w_qkv / w_proj
        round_setup<<<NSETUP4 / 256, 256>>>((const float4*)x,
                                            (const float4*)w_qkv,
                                            (const float4*)w_proj);
    }
    {   // 1) QKV GEMM (round-9 proven) + head-major scatter (Q/K fp16)
        dim3 grid(QKVN / 128, TOK / 128);
        gemm_tc<0><<<grid, 256>>>(b_qkv, nullptr, TOK, QKVN, DIM_);
    }
    {   // 2) attention: fp16 MMA1 + tf32 MMA2
        dim3 grid(N_ / 128, H_, B_);
        attn_mma_kernel<<<grid, 256, ATTN_SMEM_BYTES>>>();
    }
    {   // 3) output projection (round-9 proven)
        dim3 grid(DIM_ / 128, TOK / 128);
        gemm_tc<1><<<grid, 256>>>(b_proj, out, TOK, DIM_, DIM_);
    }
}

// round 11
// speedup vs baseline: 1.4974x; 1.3035x over previous
#include <cuda_runtime.h>
#include <cuda_fp16.h>
#include <math.h>
#include <stdint.h>

#define B_    2
#define N_    4096
#define DIM_  768
#define H_    12
#define HD_   64
#define TOK   (B_ * N_)          // 8192
#define QKVN  (3 * DIM_)         // 2304

// 0.125 * log2(e): folded into Q so softmax = exp2(S)
#define QSCALE 0.18033688011112042f

// Scratch (allocation-free rule: __device__ globals)
__device__ float  g_xr    [(size_t)TOK * DIM_];        // x, tf32-rounded
__device__ float  g_wqkv_r[(size_t)DIM_ * QKVN];       // w_qkv [k][n], tf32
__device__ float  g_wproj_r[(size_t)DIM_ * DIM_];      // w_proj [k][n], tf32
__device__ __half g_Qh[(size_t)B_ * H_ * N_ * HD_];    // [b,h,n,d] fp16, pre-scaled
__device__ __half g_Kh[(size_t)B_ * H_ * N_ * HD_];    // [b,h,n,d] fp16
__device__ __half g_Vth[(size_t)B_ * H_ * HD_ * N_];   // [b,h,d,n] fp16
__device__ float  g_att[(size_t)TOK * DIM_];           // [token, h*64+d] tf32 bits

// ---------------------------------------------------------------------------
__device__ __forceinline__ uint32_t f2tf(float x) {
    uint32_t r; asm("cvt.rna.tf32.f32 %0, %1;" : "=r"(r) : "f"(x)); return r;
}
__device__ __forceinline__ float tf(float x) { return __uint_as_float(f2tf(x)); }
__device__ __forceinline__ float ex2f(float x) {
    float r; asm("ex2.approx.f32 %0, %1;" : "=f"(r) : "f"(x)); return r;
}
__device__ __forceinline__ void mma_tf32(float c[4], const uint32_t a[4],
                                         uint32_t b0, uint32_t b1) {
    asm volatile(
        "mma.sync.aligned.m16n8k8.row.col.f32.tf32.tf32.f32 "
        "{%0,%1,%2,%3}, {%4,%5,%6,%7}, {%8,%9}, {%0,%1,%2,%3};"
        : "+f"(c[0]), "+f"(c[1]), "+f"(c[2]), "+f"(c[3])
        : "r"(a[0]), "r"(a[1]), "r"(a[2]), "r"(a[3]), "r"(b0), "r"(b1));
}
__device__ __forceinline__ void mma_f16(float c[4], const uint32_t a[4],
                                        uint32_t b0, uint32_t b1) {
    asm volatile(
        "mma.sync.aligned.m16n8k16.row.col.f32.f16.f16.f32 "
        "{%0,%1,%2,%3}, {%4,%5,%6,%7}, {%8,%9}, {%0,%1,%2,%3};"
        : "+f"(c[0]), "+f"(c[1]), "+f"(c[2]), "+f"(c[3])
        : "r"(a[0]), "r"(a[1]), "r"(a[2]), "r"(a[3]), "r"(b0), "r"(b1));
}
__device__ __forceinline__ void ldsm4(uint32_t r[4], uint32_t addr) {
    asm volatile("ldmatrix.sync.aligned.m8n8.x4.shared.b16 {%0,%1,%2,%3}, [%4];"
        : "=r"(r[0]), "=r"(r[1]), "=r"(r[2]), "=r"(r[3]) : "r"(addr));
}
#define CP_ASYNC16(dst, src) \
    asm volatile("cp.async.cg.shared.global [%0], [%1], 16;" :: "r"(dst), "l"(src) : "memory")
#define CP_COMMIT() asm volatile("cp.async.commit_group;" ::: "memory")
template <int n>
__device__ __forceinline__ void cp_wait() {
    asm volatile("cp.async.wait_group %0;" :: "n"(n) : "memory");
}

// ---------------------------------------------------------------------------
// Setup: elementwise tf32 pre-round of x, w_qkv, w_proj (proven).
// ---------------------------------------------------------------------------
#define NX4 (TOK * DIM_ / 4)
#define NQ4 (DIM_ * QKVN / 4)
#define NP4 (DIM_ * DIM_ / 4)
#define NSETUP4 (NX4 + NQ4 + NP4)

__global__ void round_setup(const float4* __restrict__ x,
                            const float4* __restrict__ wq,
                            const float4* __restrict__ wp)
{
    const int i = blockIdx.x * blockDim.x + threadIdx.x;
    float4 v;
    float4* dst;
    if (i < NX4)            { v = x[i];              dst = (float4*)g_xr + i; }
    else if (i < NX4 + NQ4) { v = wq[i - NX4];       dst = (float4*)g_wqkv_r + (i - NX4); }
    else if (i < NSETUP4)   { v = wp[i - NX4 - NQ4]; dst = (float4*)g_wproj_r + (i - NX4 - NQ4); }
    else return;
    *dst = make_float4(tf(v.x), tf(v.y), tf(v.z), tf(v.w));
}

// ---------------------------------------------------------------------------
// Tensor-core tf32 GEMM (proven): 128x128 tile, BK=16, 8 warps,
// register-prefetch staging, A frags via ldmatrix, B frags scalar [k][n].
// MODE 0: A=g_xr, B=g_wqkv_r, scatter QKV (Q/K/Vt fp16).
// MODE 1: A=g_att, B=g_wproj_r -> C.
// ---------------------------------------------------------------------------
#define APAD 20
#define BPAD 136

template <int MODE>
__global__ __launch_bounds__(256, 2)
void gemm_tc(const float* __restrict__ bias, float* __restrict__ C,
             int M, int Nn, int K)
{
    __shared__ __align__(16) float As[128 * APAD];
    __shared__ __align__(16) float Bs[16 * BPAD];

    const float* A  = (MODE == 0) ? g_xr : g_att;
    const float* Bm = (MODE == 0) ? g_wqkv_r : g_wproj_r;

    const int tid  = threadIdx.x;
    const int wid  = tid >> 5;
    const int lane = tid & 31;
    const int g = lane >> 2;
    const int t = lane & 3;
    const int bm = blockIdx.y * 128;
    const int bn = blockIdx.x * 128;
    const int mw = (wid & 3) * 32;
    const int nw = (wid >> 2) * 64;

    const int arow = tid >> 1;
    const int ak   = (tid & 1) * 8;
    const int bk   = tid >> 4;
    const int bn4  = (tid & 15) * 8;

    const uint32_t asb = (uint32_t)__cvta_generic_to_shared(As);
    const uint32_t lmoff = (((lane & 15) * APAD) + (lane >> 4) * 4) * 4;

    float acc[2][8][4];
    #pragma unroll
    for (int mi = 0; mi < 2; mi++)
        #pragma unroll
        for (int n = 0; n < 8; n++)
            #pragma unroll
            for (int j = 0; j < 4; j++) acc[mi][n][j] = 0.0f;

    const float* Aptr = A  + (size_t)(bm + arow) * K + ak;
    const float* Bptr = Bm + (size_t)bk * Nn + bn + bn4;

    float4 pa0 = ((const float4*)Aptr)[0];
    float4 pa1 = ((const float4*)Aptr)[1];
    float4 pb0 = ((const float4*)Bptr)[0];
    float4 pb1 = ((const float4*)Bptr)[1];

    const int nstage = K / 16;
    #pragma unroll 1
    for (int s = 0; s < nstage; ++s) {
        __syncthreads();
        {
            float* ad = As + arow * APAD + ak;
            *(float4*)(ad)     = pa0;
            *(float4*)(ad + 4) = pa1;
            float* bd = Bs + bk * BPAD + bn4;
            *(float4*)(bd)     = pb0;
            *(float4*)(bd + 4) = pb1;
        }
        __syncthreads();

        if (s + 1 < nstage) {
            const float* ap = Aptr + (s + 1) * 16;
            const float* bp = Bptr + (size_t)(s + 1) * 16 * Nn;
            pa0 = ((const float4*)ap)[0];
            pa1 = ((const float4*)ap)[1];
            pb0 = ((const float4*)bp)[0];
            pb1 = ((const float4*)bp)[1];
        }

        #pragma unroll
        for (int kk = 0; kk < 2; kk++) {
            uint32_t af[2][4];
            #pragma unroll
            for (int mi = 0; mi < 2; mi++)
                ldsm4(af[mi], asb + ((mw + mi * 16) * APAD) * 4 + kk * 32 + lmoff);
            #pragma unroll
            for (int n = 0; n < 8; n++) {
                const uint32_t b0 = __float_as_uint(Bs[(kk * 8 + t)     * BPAD + nw + n * 8 + g]);
                const uint32_t b1 = __float_as_uint(Bs[(kk * 8 + t + 4) * BPAD + nw + n * 8 + g]);
                mma_tf32(acc[0][n], af[0], b0, b1);
                mma_tf32(acc[1][n], af[1], b0, b1);
            }
        }
    }

    if (MODE == 1) {
        #pragma unroll
        for (int mi = 0; mi < 2; mi++) {
            const int r0 = bm + mw + mi * 16 + g;
            #pragma unroll
            for (int n = 0; n < 8; n++) {
                const int col = bn + nw + n * 8 + 2 * t;
                const float bb0 = bias[col], bb1 = bias[col + 1];
                *(float2*)(C + (size_t)r0 * Nn + col) =
                    make_float2(acc[mi][n][0] + bb0, acc[mi][n][1] + bb1);
                *(float2*)(C + (size_t)(r0 + 8) * Nn + col) =
                    make_float2(acc[mi][n][2] + bb0, acc[mi][n][3] + bb1);
            }
        }
    } else {
        const int region = (bn + nw) >> 6;
        const int which  = region / H_;
        const int h      = region % H_;
        #pragma unroll
        for (int mi = 0; mi < 2; mi++) {
            #pragma unroll
            for (int jr = 0; jr < 2; jr++) {
                const int row = bm + mw + mi * 16 + g + jr * 8;
                const int b   = row >> 12;
                const int ntk = row & (N_ - 1);
                #pragma unroll
                for (int n = 0; n < 8; n++) {
                    const int dd  = (nw + n * 8 + 2 * t) & 63;
                    const int col = bn + nw + n * 8 + 2 * t;
                    const float v0 = acc[mi][n][jr * 2 + 0] + bias[col];
                    const float v1 = acc[mi][n][jr * 2 + 1] + bias[col + 1];
                    const size_t nd = (((size_t)(b * H_ + h) * N_) + ntk) * HD_ + dd;
                    if (which == 0) {
                        *(__half2*)&g_Qh[nd] = __floats2half2_rn(v0 * QSCALE, v1 * QSCALE);
                    } else if (which == 1) {
                        *(__half2*)&g_Kh[nd] = __floats2half2_rn(v0, v1);
                    } else {
                        __half* dst = g_Vth + (((size_t)(b * H_ + h) * HD_) + dd) * N_ + ntk;
                        dst[0]  = __float2half_rn(v0);
                        dst[N_] = __float2half_rn(v1);
                    }
                }
            }
        }
    }
}

// ---------------------------------------------------------------------------
// Flash attention: full fp16 math (m16n8k16 MMA1+MMA2), fp32 accumulate.
// CTA = 256 thr (8 warps) = 128 queries x 1 head; warp owns 16 query rows.
// 64-key tiles, cp.async double-buffered, 2 CTAs/SM. No online max.
// ---------------------------------------------------------------------------
#define ROWB 144                         // bytes per 64-fp16 row (+8 pad halves)
#define KTILE_B (64 * ROWB)              // 9216 B
#define VTILE_B (64 * ROWB)              // 9216 B
#define BUF_B   (KTILE_B + VTILE_B)      // 18432 B
#define SM_P_B  (2 * BUF_B)              // 36864 B
#define ATTN_SMEM_BYTES (SM_P_B + 8 * 16 * ROWB)   // 55296 B

__global__ __launch_bounds__(256, 2)
void attn_mma_kernel()
{
    extern __shared__ __align__(16) float sm[];
    const uint32_t sb = (uint32_t)__cvta_generic_to_shared(sm);

    const int tid  = threadIdx.x;
    const int wid  = tid >> 5;
    const int lane = tid & 31;
    const int g = lane >> 2;
    const int t = lane & 3;
    const int g4 = lane >> 3;

    const int h = blockIdx.y, b = blockIdx.z;
    const int m0 = blockIdx.x * 128;
    const size_t hb = (size_t)(b * H_ + h) * N_ * HD_;

    const __half* Kg  = g_Kh + hb;
    const __half* Vtg = g_Vth + hb;

    // fp16 B-frag ldsm lane offset (proven K pattern): rows (l&7)+(g4>>1)*8, 16B half (g4&1)
    const uint32_t bfoff = ((lane & 7) + ((g4 >> 1) << 3)) * ROWB + (g4 & 1) * 16;
    // P fp16 A-frag ldsm lane offset: rows lane&15, 16B half lane>>4
    const uint32_t poff = sb + SM_P_B + wid * (16 * ROWB)
                        + (lane & 15) * ROWB + (lane >> 4) * 16;
    __half* Pw = (__half*)sm + SM_P_B / 2 + wid * 16 * (ROWB / 2);

    // --- Q fp16 fragments (4 k16-chunks x 4 regs), straight from gmem ---
    const __half* Qg = g_Qh + hb + (size_t)(m0 + wid * 16) * HD_;
    uint32_t qa[4][4];
    #pragma unroll
    for (int kt = 0; kt < 4; kt++) {
        qa[kt][0] = *(const uint32_t*)(Qg + (size_t)g * HD_       + kt * 16 + 2 * t);
        qa[kt][1] = *(const uint32_t*)(Qg + (size_t)(g + 8) * HD_ + kt * 16 + 2 * t);
        qa[kt][2] = *(const uint32_t*)(Qg + (size_t)g * HD_       + kt * 16 + 2 * t + 8);
        qa[kt][3] = *(const uint32_t*)(Qg + (size_t)(g + 8) * HD_ + kt * 16 + 2 * t + 8);
    }

    float oacc[8][4];
    #pragma unroll
    for (int n = 0; n < 8; n++)
        #pragma unroll
        for (int j = 0; j < 4; j++) oacc[n][j] = 0.0f;
    float lsum0 = 0.0f, lsum1 = 0.0f;

    {   // prefetch tile 0: K and V each 512 16B-chunks (64 rows x 8)
        #pragma unroll
        for (int i = 0; i < 2; i++) {
            const int c = tid + i * 256;
            const int r = c >> 3, q = c & 7;
            CP_ASYNC16(sb + r * ROWB + q * 16, Kg + (size_t)r * HD_ + q * 8);
            CP_ASYNC16(sb + KTILE_B + r * ROWB + q * 16, Vtg + (size_t)r * N_ + q * 8);
        }
        CP_COMMIT();
    }

    #pragma unroll 1
    for (int it = 0; it < 64; ++it) {
        __syncthreads();    // all warps done with the other buffer

        if (it + 1 < 64) {
            const uint32_t bo = ((it + 1) & 1) * BUF_B;
            const __half* Kt = Kg + (size_t)((it + 1) * 64) * HD_;
            const __half* Vt = Vtg + (it + 1) * 64;
            #pragma unroll
            for (int i = 0; i < 2; i++) {
                const int c = tid + i * 256;
                const int r = c >> 3, q = c & 7;
                CP_ASYNC16(sb + bo + r * ROWB + q * 16, Kt + (size_t)r * HD_ + q * 8);
                CP_ASYNC16(sb + bo + KTILE_B + r * ROWB + q * 16, Vt + (size_t)r * N_ + q * 8);
            }
            CP_COMMIT();
            cp_wait<1>();
        } else {
            cp_wait<0>();
        }
        __syncthreads();    // tile it visible

        const uint32_t ksb = sb + (it & 1) * BUF_B;
        const uint32_t kla = ksb + bfoff;
        const uint32_t vla = ksb + KTILE_B + bfoff;

        // --- MMA1 (fp16): S[16 x 64] = Q * K^T ---
        float sacc[8][4];
        #pragma unroll
        for (int n = 0; n < 8; n++)
            #pragma unroll
            for (int j = 0; j < 4; j++) sacc[n][j] = 0.0f;

        #pragma unroll
        for (int kt = 0; kt < 4; kt++) {
            #pragma unroll
            for (int jp = 0; jp < 4; jp++) {
                uint32_t f[4];
                ldsm4(f, kla + jp * (16 * ROWB) + kt * 32);
                mma_f16(sacc[2 * jp],     qa[kt], f[0], f[1]);
                mma_f16(sacc[2 * jp + 1], qa[kt], f[2], f[3]);
            }
        }

        // --- softmax: P = exp2(S) -> per-warp smem (fp16) ---
        #pragma unroll
        for (int n = 0; n < 8; n++) {
            const float e0 = ex2f(sacc[n][0]);
            const float e1 = ex2f(sacc[n][1]);
            const float e2 = ex2f(sacc[n][2]);
            const float e3 = ex2f(sacc[n][3]);
            lsum0 += e0 + e1;
            lsum1 += e2 + e3;
            *(__half2*)&Pw[g * (ROWB / 2) + n * 8 + 2 * t] = __floats2half2_rn(e0, e1);
            *(__half2*)&Pw[(g + 8) * (ROWB / 2) + n * 8 + 2 * t] = __floats2half2_rn(e2, e3);
        }
        __syncwarp();

        // --- MMA2 (fp16): O[16 x 64] += P * V ---
        #pragma unroll
        for (int kt = 0; kt < 4; kt++) {
            uint32_t pa[4];
            ldsm4(pa, poff + kt * 32);
            #pragma unroll
            for (int jp = 0; jp < 4; jp++) {
                uint32_t f[4];
                ldsm4(f, vla + jp * (16 * ROWB) + kt * 32);
                mma_f16(oacc[2 * jp],     pa, f[0], f[1]);
                mma_f16(oacc[2 * jp + 1], pa, f[2], f[3]);
            }
        }
    }

    lsum0 += __shfl_xor_sync(0xFFFFFFFF, lsum0, 1);
    lsum0 += __shfl_xor_sync(0xFFFFFFFF, lsum0, 2);
    lsum1 += __shfl_xor_sync(0xFFFFFFFF, lsum1, 1);
    lsum1 += __shfl_xor_sync(0xFFFFFFFF, lsum1, 2);
    const float inv0 = 1.0f / lsum0;
    const float inv1 = 1.0f / lsum1;

    const size_t row0 = (size_t)(b * N_ + m0 + wid * 16 + g);
    float* o0 = g_att + row0 * DIM_ + h * HD_;
    float* o1 = o0 + 8 * DIM_;
    #pragma unroll
    for (int n = 0; n < 8; n++) {
        *(float2*)(o0 + n * 8 + 2 * t) =
            make_float2(tf(oacc[n][0] * inv0), tf(oacc[n][1] * inv0));
        *(float2*)(o1 + n * 8 + 2 * t) =
            make_float2(tf(oacc[n][2] * inv1), tf(oacc[n][3] * inv1));
    }
}

// ---------------------------------------------------------------------------
extern "C" void kernel_launch(void* const* d_in, const int* in_sizes, int n_in,
                              void* d_out, int out_size)
{
    const float* x      = (const float*)d_in[0];
    const float* w_qkv  = (const float*)d_in[1];
    const float* b_qkv  = (const float*)d_in[2];
    const float* w_proj = (const float*)d_in[3];
    const float* b_proj = (const float*)d_in[4];
    float* out = (float*)d_out;

    cudaFuncSetAttribute(attn_mma_kernel,
                         cudaFuncAttributeMaxDynamicSharedMemorySize, ATTN_SMEM_BYTES);

    {   // 0) elementwise tf32 pre-round of x / w_qkv / w_proj
        round_setup<<<NSETUP4 / 256, 256>>>((const float4*)x,
                                            (const float4*)w_qkv,
                                            (const float4*)w_proj);
    }
    {   // 1) QKV GEMM (proven) + head-major scatter (Q/K/Vt fp16)
        dim3 grid(QKVN / 128, TOK / 128);
        gemm_tc<0><<<grid, 256>>>(b_qkv, nullptr, TOK, QKVN, DIM_);
    }
    {   // 2) attention: full fp16 mma (QK + PV), fp32 accum
        dim3 grid(N_ / 128, H_, B_);
        attn_mma_kernel<<<grid, 256, ATTN_SMEM_BYTES>>>();
    }
    {   // 3) output projection (proven)
        dim3 grid(DIM_ / 128, TOK / 128);
        gemm_tc<1><<<grid, 256>>>(b_proj, out, TOK, DIM_, DIM_);
    }
}

// round 12
// speedup vs baseline: 1.9949x; 1.3323x over previous
#include <cuda_runtime.h>
#include <cuda_fp16.h>
#include <math.h>
#include <stdint.h>

#define B_    2
#define N_    4096
#define DIM_  768
#define H_    12
#define HD_   64
#define TOK   (B_ * N_)          // 8192
#define QKVN  (3 * DIM_)         // 2304

// 0.125 * log2(e): folded into Q so softmax = exp2(S)
#define QSCALE 0.18033688011112042f

// Scratch (allocation-free rule: __device__ globals)
__device__ __half g_xh    [(size_t)TOK * DIM_];        // x, fp16 [row][k]
__device__ __half g_wqkvh [(size_t)DIM_ * QKVN];       // w_qkv fp16 [k][n]
__device__ __half g_wprojh[(size_t)DIM_ * DIM_];       // w_proj fp16 [k][n]
__device__ __half g_Qh[(size_t)B_ * H_ * N_ * HD_];    // [b,h,n,d] fp16, pre-scaled
__device__ __half g_Kh[(size_t)B_ * H_ * N_ * HD_];    // [b,h,n,d] fp16
__device__ __half g_Vth[(size_t)B_ * H_ * HD_ * N_];   // [b,h,d,n] fp16
__device__ __half g_att[(size_t)TOK * DIM_];           // [token, h*64+d] fp16

// ---------------------------------------------------------------------------
__device__ __forceinline__ float ex2f(float x) {
    float r; asm("ex2.approx.f32 %0, %1;" : "=f"(r) : "f"(x)); return r;
}
__device__ __forceinline__ void mma_f16(float c[4], const uint32_t a[4],
                                        uint32_t b0, uint32_t b1) {
    asm volatile(
        "mma.sync.aligned.m16n8k16.row.col.f32.f16.f16.f32 "
        "{%0,%1,%2,%3}, {%4,%5,%6,%7}, {%8,%9}, {%0,%1,%2,%3};"
        : "+f"(c[0]), "+f"(c[1]), "+f"(c[2]), "+f"(c[3])
        : "r"(a[0]), "r"(a[1]), "r"(a[2]), "r"(a[3]), "r"(b0), "r"(b1));
}
__device__ __forceinline__ void ldsm4(uint32_t r[4], uint32_t addr) {
    asm volatile("ldmatrix.sync.aligned.m8n8.x4.shared.b16 {%0,%1,%2,%3}, [%4];"
        : "=r"(r[0]), "=r"(r[1]), "=r"(r[2]), "=r"(r[3]) : "r"(addr));
}
__device__ __forceinline__ void ldsm4t(uint32_t r[4], uint32_t addr) {
    asm volatile("ldmatrix.sync.aligned.m8n8.x4.trans.shared.b16 {%0,%1,%2,%3}, [%4];"
        : "=r"(r[0]), "=r"(r[1]), "=r"(r[2]), "=r"(r[3]) : "r"(addr));
}
#define CP_ASYNC16(dst, src) \
    asm volatile("cp.async.cg.shared.global [%0], [%1], 16;" :: "r"(dst), "l"(src) : "memory")
#define CP_COMMIT() asm volatile("cp.async.commit_group;" ::: "memory")
template <int n>
__device__ __forceinline__ void cp_wait() {
    asm volatile("cp.async.wait_group %0;" :: "n"(n) : "memory");
}

// ---------------------------------------------------------------------------
// Setup: elementwise fp32 -> fp16 of x, w_qkv, w_proj.
// ---------------------------------------------------------------------------
#define NX4 (TOK * DIM_ / 4)
#define NQ4 (DIM_ * QKVN / 4)
#define NP4 (DIM_ * DIM_ / 4)
#define NSETUP4 (NX4 + NQ4 + NP4)

__global__ void setup_h(const float4* __restrict__ x,
                        const float4* __restrict__ wq,
                        const float4* __restrict__ wp)
{
    const int i = blockIdx.x * blockDim.x + threadIdx.x;
    float4 v;
    __half* dst;
    if (i < NX4)            { v = x[i];              dst = g_xh     + 4 * (size_t)i; }
    else if (i < NX4 + NQ4) { v = wq[i - NX4];       dst = g_wqkvh  + 4 * (size_t)(i - NX4); }
    else if (i < NSETUP4)   { v = wp[i - NX4 - NQ4]; dst = g_wprojh + 4 * (size_t)(i - NX4 - NQ4); }
    else return;
    *(__half2*)(dst)     = __floats2half2_rn(v.x, v.y);
    *(__half2*)(dst + 2) = __floats2half2_rn(v.z, v.w);
}

// ---------------------------------------------------------------------------
// fp16 tensor-core GEMM: C = A @ B + bias, fp32 accumulate.
// 128x128 CTA tile, BK=32, 8 warps (warp tile 32x64), reg-prefetch staging.
// A smem [row][k] (80 B rows), frags via ldsm.x4 (proven P pattern).
// B smem [k][n] (272 B rows), frags via ldsm.x4.trans (canonical row-major B).
// MODE 0: A=g_xh, B=g_wqkvh, scatter QKV. MODE 1: A=g_att, B=g_wprojh -> C.
// ---------------------------------------------------------------------------
#define AROWB 80                    // 32 halves (64 B) + 16 pad
#define BROWB 272                   // 128 halves (256 B) + 16 pad
#define ASTG_B (128 * AROWB)        // 10240 B
#define BSTG_B (32 * BROWB)         //  8704 B

template <int MODE>
__global__ __launch_bounds__(256, 2)
void gemm_h(const float* __restrict__ bias, float* __restrict__ C,
            int M, int Nn, int K)
{
    __shared__ __align__(16) char sA[ASTG_B];
    __shared__ __align__(16) char sB[BSTG_B];

    const __half* A  = (MODE == 0) ? g_xh : g_att;
    const __half* Bm = (MODE == 0) ? g_wqkvh : g_wprojh;

    const int tid  = threadIdx.x;
    const int wid  = tid >> 5;
    const int lane = tid & 31;
    const int g = lane >> 2;
    const int t = lane & 3;
    const int bm = blockIdx.y * 128;
    const int bn = blockIdx.x * 128;
    const int mw = (wid & 3) * 32;
    const int nw = (wid >> 2) * 64;

    const uint32_t asb = (uint32_t)__cvta_generic_to_shared(sA);
    const uint32_t bsb = (uint32_t)__cvta_generic_to_shared(sB);
    // A-frag lane offset: rows lane&15 (m0/m1), 16B k-half lane>>4 (m2/m3)
    const uint32_t aoff = (lane & 15) * AROWB + (lane >> 4) * 16;
    // B-frag (trans) lane offset: k-rows (l&7)+((l>>3)&1)*8, n-8group (l>>4)
    const uint32_t boff = ((lane & 7) + ((lane >> 3) & 1) * 8) * BROWB + (lane >> 4) * 16;

    // staging: A 512 chunks (128 rows x 4), B 512 chunks (32 rows x 16); 2 each/thread
    const int ar = tid >> 1, aq = (tid & 1) * 2;      // A: row, chunk pair start
    const int br = tid >> 3, bq = (tid & 7) * 2;      // B: row, chunk pair start

    float acc[2][8][4];
    #pragma unroll
    for (int mi = 0; mi < 2; mi++)
        #pragma unroll
        for (int n = 0; n < 8; n++)
            #pragma unroll
            for (int j = 0; j < 4; j++) acc[mi][n][j] = 0.0f;

    const __half* Aptr = A  + (size_t)(bm + ar) * K + aq * 8;
    const __half* Bptr = Bm + (size_t)br * Nn + bn + bq * 8;

    // prefetch stage 0
    uint4 pa0 = ((const uint4*)Aptr)[0];
    uint4 pa1 = ((const uint4*)Aptr)[1];
    uint4 pb0 = ((const uint4*)Bptr)[0];
    uint4 pb1 = ((const uint4*)Bptr)[1];

    const int nstage = K / 32;
    #pragma unroll 1
    for (int s = 0; s < nstage; ++s) {
        __syncthreads();
        {
            *(uint4*)(sA + ar * AROWB + aq * 16)        = pa0;
            *(uint4*)(sA + ar * AROWB + aq * 16 + 16)   = pa1;
            *(uint4*)(sB + br * BROWB + bq * 16)        = pb0;
            *(uint4*)(sB + br * BROWB + bq * 16 + 16)   = pb1;
        }
        __syncthreads();

        if (s + 1 < nstage) {
            const __half* ap = Aptr + (s + 1) * 32;
            const __half* bp = Bptr + (size_t)(s + 1) * 32 * Nn;
            pa0 = ((const uint4*)ap)[0];
            pa1 = ((const uint4*)ap)[1];
            pb0 = ((const uint4*)bp)[0];
            pb1 = ((const uint4*)bp)[1];
        }

        #pragma unroll
        for (int kt = 0; kt < 2; kt++) {
            uint32_t af[2][4];
            #pragma unroll
            for (int mi = 0; mi < 2; mi++)
                ldsm4(af[mi], asb + (mw + mi * 16) * AROWB + kt * 32 + aoff);
            #pragma unroll
            for (int np = 0; np < 4; np++) {
                uint32_t bf[4];
                ldsm4t(bf, bsb + kt * 16 * BROWB + (nw + np * 16) * 2 + boff);
                mma_f16(acc[0][2 * np],     af[0], bf[0], bf[1]);
                mma_f16(acc[1][2 * np],     af[1], bf[0], bf[1]);
                mma_f16(acc[0][2 * np + 1], af[0], bf[2], bf[3]);
                mma_f16(acc[1][2 * np + 1], af[1], bf[2], bf[3]);
            }
        }
    }

    if (MODE == 1) {
        #pragma unroll
        for (int mi = 0; mi < 2; mi++) {
            const int r0 = bm + mw + mi * 16 + g;
            #pragma unroll
            for (int n = 0; n < 8; n++) {
                const int col = bn + nw + n * 8 + 2 * t;
                const float bb0 = bias[col], bb1 = bias[col + 1];
                *(float2*)(C + (size_t)r0 * Nn + col) =
                    make_float2(acc[mi][n][0] + bb0, acc[mi][n][1] + bb1);
                *(float2*)(C + (size_t)(r0 + 8) * Nn + col) =
                    make_float2(acc[mi][n][2] + bb0, acc[mi][n][3] + bb1);
            }
        }
    } else {
        const int region = (bn + nw) >> 6;
        const int which  = region / H_;
        const int h      = region % H_;
        #pragma unroll
        for (int mi = 0; mi < 2; mi++) {
            #pragma unroll
            for (int jr = 0; jr < 2; jr++) {
                const int row = bm + mw + mi * 16 + g + jr * 8;
                const int b   = row >> 12;
                const int ntk = row & (N_ - 1);
                #pragma unroll
                for (int n = 0; n < 8; n++) {
                    const int dd  = (nw + n * 8 + 2 * t) & 63;
                    const int col = bn + nw + n * 8 + 2 * t;
                    const float v0 = acc[mi][n][jr * 2 + 0] + bias[col];
                    const float v1 = acc[mi][n][jr * 2 + 1] + bias[col + 1];
                    const size_t nd = (((size_t)(b * H_ + h) * N_) + ntk) * HD_ + dd;
                    if (which == 0) {
                        *(__half2*)&g_Qh[nd] = __floats2half2_rn(v0 * QSCALE, v1 * QSCALE);
                    } else if (which == 1) {
                        *(__half2*)&g_Kh[nd] = __floats2half2_rn(v0, v1);
                    } else {
                        __half* dst = g_Vth + (((size_t)(b * H_ + h) * HD_) + dd) * N_ + ntk;
                        dst[0]  = __float2half_rn(v0);
                        dst[N_] = __float2half_rn(v1);
                    }
                }
            }
        }
    }
}

// ---------------------------------------------------------------------------
// Flash attention (round-11 proven): full fp16 mma, fp32 accumulate.
// Only delta: g_att stores are fp16 (feeds fp16 gemm<1> directly).
// ---------------------------------------------------------------------------
#define ROWB 144
#define KTILE_B (64 * ROWB)
#define VTILE_B (64 * ROWB)
#define BUF_B   (KTILE_B + VTILE_B)
#define SM_P_B  (2 * BUF_B)
#define ATTN_SMEM_BYTES (SM_P_B + 8 * 16 * ROWB)   // 55296 B

__global__ __launch_bounds__(256, 2)
void attn_mma_kernel()
{
    extern __shared__ __align__(16) float sm[];
    const uint32_t sb = (uint32_t)__cvta_generic_to_shared(sm);

    const int tid  = threadIdx.x;
    const int wid  = tid >> 5;
    const int lane = tid & 31;
    const int g = lane >> 2;
    const int t = lane & 3;
    const int g4 = lane >> 3;

    const int h = blockIdx.y, b = blockIdx.z;
    const int m0 = blockIdx.x * 128;
    const size_t hb = (size_t)(b * H_ + h) * N_ * HD_;

    const __half* Kg  = g_Kh + hb;
    const __half* Vtg = g_Vth + hb;

    const uint32_t bfoff = ((lane & 7) + ((g4 >> 1) << 3)) * ROWB + (g4 & 1) * 16;
    const uint32_t poff = sb + SM_P_B + wid * (16 * ROWB)
                        + (lane & 15) * ROWB + (lane >> 4) * 16;
    __half* Pw = (__half*)sm + SM_P_B / 2 + wid * 16 * (ROWB / 2);

    const __half* Qg = g_Qh + hb + (size_t)(m0 + wid * 16) * HD_;
    uint32_t qa[4][4];
    #pragma unroll
    for (int kt = 0; kt < 4; kt++) {
        qa[kt][0] = *(const uint32_t*)(Qg + (size_t)g * HD_       + kt * 16 + 2 * t);
        qa[kt][1] = *(const uint32_t*)(Qg + (size_t)(g + 8) * HD_ + kt * 16 + 2 * t);
        qa[kt][2] = *(const uint32_t*)(Qg + (size_t)g * HD_       + kt * 16 + 2 * t + 8);
        qa[kt][3] = *(const uint32_t*)(Qg + (size_t)(g + 8) * HD_ + kt * 16 + 2 * t + 8);
    }

    float oacc[8][4];
    #pragma unroll
    for (int n = 0; n < 8; n++)
        #pragma unroll
        for (int j = 0; j < 4; j++) oacc[n][j] = 0.0f;
    float lsum0 = 0.0f, lsum1 = 0.0f;

    {   // prefetch tile 0
        #pragma unroll
        for (int i = 0; i < 2; i++) {
            const int c = tid + i * 256;
            const int r = c >> 3, q = c & 7;
            CP_ASYNC16(sb + r * ROWB + q * 16, Kg + (size_t)r * HD_ + q * 8);
            CP_ASYNC16(sb + KTILE_B + r * ROWB + q * 16, Vtg + (size_t)r * N_ + q * 8);
        }
        CP_COMMIT();
    }

    #pragma unroll 1
    for (int it = 0; it < 64; ++it) {
        __syncthreads();

        if (it + 1 < 64) {
            const uint32_t bo = ((it + 1) & 1) * BUF_B;
            const __half* Kt = Kg + (size_t)((it + 1) * 64) * HD_;
            const __half* Vt = Vtg + (it + 1) * 64;
            #pragma unroll
            for (int i = 0; i < 2; i++) {
                const int c = tid + i * 256;
                const int r = c >> 3, q = c & 7;
                CP_ASYNC16(sb + bo + r * ROWB + q * 16, Kt + (size_t)r * HD_ + q * 8);
                CP_ASYNC16(sb + bo + KTILE_B + r * ROWB + q * 16, Vt + (size_t)r * N_ + q * 8);
            }
            CP_COMMIT();
            cp_wait<1>();
        } else {
            cp_wait<0>();
        }
        __syncthreads();

        const uint32_t ksb = sb + (it & 1) * BUF_B;
        const uint32_t kla = ksb + bfoff;
        const uint32_t vla = ksb + KTILE_B + bfoff;

        float sacc[8][4];
        #pragma unroll
        for (int n = 0; n < 8; n++)
            #pragma unroll
            for (int j = 0; j < 4; j++) sacc[n][j] = 0.0f;

        #pragma unroll
        for (int kt = 0; kt < 4; kt++) {
            #pragma unroll
            for (int jp = 0; jp < 4; jp++) {
                uint32_t f[4];
                ldsm4(f, kla + jp * (16 * ROWB) + kt * 32);
                mma_f16(sacc[2 * jp],     qa[kt], f[0], f[1]);
                mma_f16(sacc[2 * jp + 1], qa[kt], f[2], f[3]);
            }
        }

        #pragma unroll
        for (int n = 0; n < 8; n++) {
            const float e0 = ex2f(sacc[n][0]);
            const float e1 = ex2f(sacc[n][1]);
            const float e2 = ex2f(sacc[n][2]);
            const float e3 = ex2f(sacc[n][3]);
            lsum0 += e0 + e1;
            lsum1 += e2 + e3;
            *(__half2*)&Pw[g * (ROWB / 2) + n * 8 + 2 * t] = __floats2half2_rn(e0, e1);
            *(__half2*)&Pw[(g + 8) * (ROWB / 2) + n * 8 + 2 * t] = __floats2half2_rn(e2, e3);
        }
        __syncwarp();

        #pragma unroll
        for (int kt = 0; kt < 4; kt++) {
            uint32_t pa[4];
            ldsm4(pa, poff + kt * 32);
            #pragma unroll
            for (int jp = 0; jp < 4; jp++) {
                uint32_t f[4];
                ldsm4(f, vla + jp * (16 * ROWB) + kt * 32);
                mma_f16(oacc[2 * jp],     pa, f[0], f[1]);
                mma_f16(oacc[2 * jp + 1], pa, f[2], f[3]);
            }
        }
    }

    lsum0 += __shfl_xor_sync(0xFFFFFFFF, lsum0, 1);
    lsum0 += __shfl_xor_sync(0xFFFFFFFF, lsum0, 2);
    lsum1 += __shfl_xor_sync(0xFFFFFFFF, lsum1, 1);
    lsum1 += __shfl_xor_sync(0xFFFFFFFF, lsum1, 2);
    const float inv0 = 1.0f / lsum0;
    const float inv1 = 1.0f / lsum1;

    const size_t row0 = (size_t)(b * N_ + m0 + wid * 16 + g);
    __half* o0 = g_att + row0 * DIM_ + h * HD_;
    __half* o1 = o0 + 8 * DIM_;
    #pragma unroll
    for (int n = 0; n < 8; n++) {
        *(__half2*)(o0 + n * 8 + 2 * t) =
            __floats2half2_rn(oacc[n][0] * inv0, oacc[n][1] * inv0);
        *(__half2*)(o1 + n * 8 + 2 * t) =
            __floats2half2_rn(oacc[n][2] * inv1, oacc[n][3] * inv1);
    }
}

// ---------------------------------------------------------------------------
extern "C" void kernel_launch(void* const* d_in, const int* in_sizes, int n_in,
                              void* d_out, int out_size)
{
    const float* x      = (const float*)d_in[0];
    const float* w_qkv  = (const float*)d_in[1];
    const float* b_qkv  = (const float*)d_in[2];
    const float* w_proj = (const float*)d_in[3];
    const float* b_proj = (const float*)d_in[4];
    float* out = (float*)d_out;

    cudaFuncSetAttribute(attn_mma_kernel,
                         cudaFuncAttributeMaxDynamicSharedMemorySize, ATTN_SMEM_BYTES);

    {   // 0) fp32 -> fp16 of x / w_qkv / w_proj
        setup_h<<<NSETUP4 / 256, 256>>>((const float4*)x,
                                        (const float4*)w_qkv,
                                        (const float4*)w_proj);
    }
    {   // 1) QKV GEMM (fp16 mma) + head-major scatter
        dim3 grid(QKVN / 128, TOK / 128);
        gemm_h<0><<<grid, 256>>>(b_qkv, nullptr, TOK, QKVN, DIM_);
    }
    {   // 2) attention: full fp16 mma, fp16 g_att out
        dim3 grid(N_ / 128, H_, B_);
        attn_mma_kernel<<<grid, 256, ATTN_SMEM_BYTES>>>();
    }
    {   // 3) output projection (fp16 mma)
        dim3 grid(DIM_ / 128, TOK / 128);
        gemm_h<1><<<grid, 256>>>(b_proj, out, TOK, DIM_, DIM_);
    }
}